// round 10
// baseline (speedup 1.0000x reference)
#include <cuda_runtime.h>
#include <cuda_bf16.h>
#include <cstdint>

// HSMNet cost-volume + channel-sum + softmax disparity regression, fused.
// B=4, C=32, H=80, W=160, D=24. Output [B,H,W] f32.
//
// R10: R9 compute (thread = wpair x dg4 x cg2, conflict-free LDS.64, shfl
// merges) with LDG staging replaced by cp.async.bulk.shared::cta + mbarrier:
// 64 bulk copies (32 tgt x 256B, 32 ref x 160B) issued by thread 0. Removes
// the front-batched LDG burst (cross-CTA L1tex-queue spread) and ~130 staging
// instructions per thread. q=0 left halo (g<0) is zero-filled via STS; its
// cost entries are overwritten by validity selects anyway.

#define Bc 4
#define Cc 32
#define Hc 80
#define Wc 160
#define Dc 24
#define QW 40                 // pixels per CTA (quarter row)
#define NT 160
#define TROW 64               // tgt cols staged: [w_start-24, w_start+40)
#define RROW 40               // ref cols staged: [w_start, w_start+40)
#define CPT 16                // channels per thread

__global__ __launch_bounds__(NT, 9)
void hsm_dispreg_kernel(const float* __restrict__ ref,
                        const float* __restrict__ tgt,
                        float* __restrict__ out)
{
    __shared__ __align__(16) float st[Cc * TROW];   // 2048 floats
    __shared__ __align__(16) float sr[Cc * RROW];   // 1280 floats
    __shared__ __align__(8)  unsigned long long mbar;

    const int q   = blockIdx.x;              // 0..3
    const int h   = blockIdx.y;
    const int b   = blockIdx.z;
    const int tid = threadIdx.x;

    const int w_start = q * QW;
    const int rowbase = (b * Cc * Hc + h) * Wc;
    const int HW = Hc * Wc;
    const int g0 = w_start - 24;

    const uint32_t mbar_u = (uint32_t)__cvta_generic_to_shared(&mbar);
    const uint32_t st_u   = (uint32_t)__cvta_generic_to_shared(st);
    const uint32_t sr_u   = (uint32_t)__cvta_generic_to_shared(sr);

    if (tid == 0) {
        asm volatile("mbarrier.init.shared.b64 [%0], %1;" :: "r"(mbar_u), "r"(1) : "memory");
    }
    // q==0: zero-fill the 24-float left halo per channel (g<0 region).
    if (q == 0) {
#pragma unroll
        for (int k = 0; k < 5; ++k) {
            const int idx = tid + k * NT;        // 0..767 covers 32*24=768
            if (idx < Cc * 24) {
                const int c = idx / 24;
                const int l = idx - c * 24;
                st[c * TROW + l] = 0.0f;
            }
        }
    }
    __syncthreads();

    if (tid == 0) {
        const int tgt_bytes = (q == 0) ? 160 : 256;   // per channel
        const int tx = Cc * tgt_bytes + Cc * 160;
        asm volatile("mbarrier.arrive.expect_tx.shared.b64 _, [%0], %1;"
                     :: "r"(mbar_u), "r"(tx) : "memory");
#pragma unroll 1
        for (int c = 0; c < Cc; ++c) {
            // tgt row: q==0 copies valid [0,40) into local offset 24; else full 64.
            const float* tsrc = tgt + rowbase + c * HW + ((q == 0) ? 0 : g0);
            const uint32_t tdst = st_u + (uint32_t)(c * TROW + ((q == 0) ? 24 : 0)) * 4u;
            asm volatile(
                "cp.async.bulk.shared::cta.global.mbarrier::complete_tx::bytes "
                "[%0], [%1], %2, [%3];"
                :: "r"(tdst), "l"(tsrc), "r"(tgt_bytes), "r"(mbar_u) : "memory");
            // ref row: 40 floats = 160B.
            const float* rsrc = ref + rowbase + c * HW + w_start;
            const uint32_t rdst = sr_u + (uint32_t)(c * RROW) * 4u;
            asm volatile(
                "cp.async.bulk.shared::cta.global.mbarrier::complete_tx::bytes "
                "[%0], [%1], %2, [%3];"
                :: "r"(rdst), "l"(rsrc), "r"(160), "r"(mbar_u) : "memory");
        }
    }

    // All threads wait for completion (phase parity 0), acquire ordering.
    {
        unsigned ok;
        do {
            asm volatile(
                "{\n\t.reg .pred p;\n\t"
                "mbarrier.try_wait.parity.acquire.cta.shared::cta.b64 p, [%1], %2, 0x989680;\n\t"
                "selp.b32 %0, 1, 0, p;\n\t}"
                : "=r"(ok) : "r"(mbar_u), "r"(0u) : "memory");
        } while (!ok);
    }

    // ---- compute: identical to R9 ----
    const int lane = tid & 31;
    const int warp = tid >> 5;               // 0..4
    const int wbq  = warp * 4 + (lane & 3);  // 0..19
    const int dg   = (lane >> 2) & 3;
    const int cg   = lane >> 4;
    const int w0   = w_start + 2 * wbq;
    const int d0   = 6 * dg;

    const float* tp = st + (2 * wbq - d0 + 18);        // + c*TROW
    const float* rp = sr + 2 * wbq;                    // + c*RROW
    const int c0 = cg * CPT;

    float c00 = 0.f, c01 = 0.f, c02 = 0.f, c03 = 0.f, c04 = 0.f, c05 = 0.f;
    float c10 = 0.f, c11 = 0.f, c12 = 0.f, c13 = 0.f, c14 = 0.f, c15 = 0.f;

#pragma unroll
    for (int k = 0; k < CPT; ++k) {
        const int c = c0 + k;
        const float2 r  = *(const float2*)(rp + c * RROW);
        const float2 tA = *(const float2*)(tp + c * TROW);      // t0,t1
        const float2 tB = *(const float2*)(tp + c * TROW + 2);  // t2,t3
        const float2 tC = *(const float2*)(tp + c * TROW + 4);  // t4,t5
        const float2 tD = *(const float2*)(tp + c * TROW + 6);  // t6,t7
        c00 += fabsf(r.x - tD.x);
        c01 += fabsf(r.x - tC.y);
        c02 += fabsf(r.x - tC.x);
        c03 += fabsf(r.x - tB.y);
        c04 += fabsf(r.x - tB.x);
        c05 += fabsf(r.x - tA.y);
        c10 += fabsf(r.y - tD.y);
        c11 += fabsf(r.y - tD.x);
        c12 += fabsf(r.y - tC.y);
        c13 += fabsf(r.y - tC.x);
        c14 += fabsf(r.y - tB.y);
        c15 += fabsf(r.y - tB.x);
    }

    c00 += __shfl_xor_sync(0xffffffffu, c00, 16);
    c01 += __shfl_xor_sync(0xffffffffu, c01, 16);
    c02 += __shfl_xor_sync(0xffffffffu, c02, 16);
    c03 += __shfl_xor_sync(0xffffffffu, c03, 16);
    c04 += __shfl_xor_sync(0xffffffffu, c04, 16);
    c05 += __shfl_xor_sync(0xffffffffu, c05, 16);
    c10 += __shfl_xor_sync(0xffffffffu, c10, 16);
    c11 += __shfl_xor_sync(0xffffffffu, c11, 16);
    c12 += __shfl_xor_sync(0xffffffffu, c12, 16);
    c13 += __shfl_xor_sync(0xffffffffu, c13, 16);
    c14 += __shfl_xor_sync(0xffffffffu, c14, 16);
    c15 += __shfl_xor_sync(0xffffffffu, c15, 16);

    if (w0 < d0    ) c00 = 0.f;
    if (w0 < d0 + 1) c01 = 0.f;
    if (w0 < d0 + 2) c02 = 0.f;
    if (w0 < d0 + 3) c03 = 0.f;
    if (w0 < d0 + 4) c04 = 0.f;
    if (w0 < d0 + 5) c05 = 0.f;
    if (w0 + 1 < d0    ) c10 = 0.f;
    if (w0 + 1 < d0 + 1) c11 = 0.f;
    if (w0 + 1 < d0 + 2) c12 = 0.f;
    if (w0 + 1 < d0 + 3) c13 = 0.f;
    if (w0 + 1 < d0 + 4) c14 = 0.f;
    if (w0 + 1 < d0 + 5) c15 = 0.f;

    float m0 = fmaxf(fmaxf(fmaxf(c00, c01), fmaxf(c02, c03)), fmaxf(c04, c05));
    float m1 = fmaxf(fmaxf(fmaxf(c10, c11), fmaxf(c12, c13)), fmaxf(c14, c15));
    m0 = fmaxf(m0, __shfl_xor_sync(0xffffffffu, m0, 4));
    m0 = fmaxf(m0, __shfl_xor_sync(0xffffffffu, m0, 8));
    m1 = fmaxf(m1, __shfl_xor_sync(0xffffffffu, m1, 4));
    m1 = fmaxf(m1, __shfl_xor_sync(0xffffffffu, m1, 8));

    const float e00 = __expf(c00 - m0), e01 = __expf(c01 - m0), e02 = __expf(c02 - m0);
    const float e03 = __expf(c03 - m0), e04 = __expf(c04 - m0), e05 = __expf(c05 - m0);
    const float e10 = __expf(c10 - m1), e11 = __expf(c11 - m1), e12 = __expf(c12 - m1);
    const float e13 = __expf(c13 - m1), e14 = __expf(c14 - m1), e15 = __expf(c15 - m1);

    const float fd = (float)d0;
    float s0 = ((e00 + e01) + (e02 + e03)) + (e04 + e05);
    float n0 = fd * e00 + (fd + 1.f) * e01 + (fd + 2.f) * e02
             + (fd + 3.f) * e03 + (fd + 4.f) * e04 + (fd + 5.f) * e05;
    float s1 = ((e10 + e11) + (e12 + e13)) + (e14 + e15);
    float n1 = fd * e10 + (fd + 1.f) * e11 + (fd + 2.f) * e12
             + (fd + 3.f) * e13 + (fd + 4.f) * e14 + (fd + 5.f) * e15;

    s0 += __shfl_xor_sync(0xffffffffu, s0, 4);
    s0 += __shfl_xor_sync(0xffffffffu, s0, 8);
    n0 += __shfl_xor_sync(0xffffffffu, n0, 4);
    n0 += __shfl_xor_sync(0xffffffffu, n0, 8);
    s1 += __shfl_xor_sync(0xffffffffu, s1, 4);
    s1 += __shfl_xor_sync(0xffffffffu, s1, 8);
    n1 += __shfl_xor_sync(0xffffffffu, n1, 4);
    n1 += __shfl_xor_sync(0xffffffffu, n1, 8);

    if (dg == 0 && cg == 0) {
        float2 o;
        o.x = n0 / s0;
        o.y = n1 / s1;
        *(float2*)&out[(b * Hc + h) * Wc + w0] = o;
    }
}

extern "C" void kernel_launch(void* const* d_in, const int* in_sizes, int n_in,
                              void* d_out, int out_size)
{
    const float* ref = (const float*)d_in[0];
    const float* tgt = (const float*)d_in[1];
    float* out = (float*)d_out;

    dim3 grid(4, Hc, Bc);   // 1280 CTAs x 160 threads
    hsm_dispreg_kernel<<<grid, NT>>>(ref, tgt, out);
}

// round 11
// speedup vs baseline: 1.0025x; 1.0025x over previous
#include <cuda_runtime.h>
#include <cuda_bf16.h>
#include <cstdint>

// HSMNet cost-volume + channel-sum + softmax disparity regression, fused.
// B=4, C=32, H=80, W=160, D=24. Output [B,H,W] f32.
//
// R10: R9 compute (thread = wpair x dg4 x cg2, conflict-free LDS.64, shfl
// merges) with LDG staging replaced by cp.async.bulk.shared::cta + mbarrier:
// 64 bulk copies (32 tgt x 256B, 32 ref x 160B) issued by thread 0. Removes
// the front-batched LDG burst (cross-CTA L1tex-queue spread) and ~130 staging
// instructions per thread. q=0 left halo (g<0) is zero-filled via STS; its
// cost entries are overwritten by validity selects anyway.

#define Bc 4
#define Cc 32
#define Hc 80
#define Wc 160
#define Dc 24
#define QW 40                 // pixels per CTA (quarter row)
#define NT 160
#define TROW 64               // tgt cols staged: [w_start-24, w_start+40)
#define RROW 40               // ref cols staged: [w_start, w_start+40)
#define CPT 16                // channels per thread

__global__ __launch_bounds__(NT, 9)
void hsm_dispreg_kernel(const float* __restrict__ ref,
                        const float* __restrict__ tgt,
                        float* __restrict__ out)
{
    __shared__ __align__(16) float st[Cc * TROW];   // 2048 floats
    __shared__ __align__(16) float sr[Cc * RROW];   // 1280 floats
    __shared__ __align__(8)  unsigned long long mbar;

    const int q   = blockIdx.x;              // 0..3
    const int h   = blockIdx.y;
    const int b   = blockIdx.z;
    const int tid = threadIdx.x;

    const int w_start = q * QW;
    const int rowbase = (b * Cc * Hc + h) * Wc;
    const int HW = Hc * Wc;
    const int g0 = w_start - 24;

    const uint32_t mbar_u = (uint32_t)__cvta_generic_to_shared(&mbar);
    const uint32_t st_u   = (uint32_t)__cvta_generic_to_shared(st);
    const uint32_t sr_u   = (uint32_t)__cvta_generic_to_shared(sr);

    if (tid == 0) {
        asm volatile("mbarrier.init.shared.b64 [%0], %1;" :: "r"(mbar_u), "r"(1) : "memory");
    }
    // q==0: zero-fill the 24-float left halo per channel (g<0 region).
    if (q == 0) {
#pragma unroll
        for (int k = 0; k < 5; ++k) {
            const int idx = tid + k * NT;        // 0..767 covers 32*24=768
            if (idx < Cc * 24) {
                const int c = idx / 24;
                const int l = idx - c * 24;
                st[c * TROW + l] = 0.0f;
            }
        }
    }
    __syncthreads();

    if (tid == 0) {
        const int tgt_bytes = (q == 0) ? 160 : 256;   // per channel
        const int tx = Cc * tgt_bytes + Cc * 160;
        asm volatile("mbarrier.arrive.expect_tx.shared.b64 _, [%0], %1;"
                     :: "r"(mbar_u), "r"(tx) : "memory");
#pragma unroll 1
        for (int c = 0; c < Cc; ++c) {
            // tgt row: q==0 copies valid [0,40) into local offset 24; else full 64.
            const float* tsrc = tgt + rowbase + c * HW + ((q == 0) ? 0 : g0);
            const uint32_t tdst = st_u + (uint32_t)(c * TROW + ((q == 0) ? 24 : 0)) * 4u;
            asm volatile(
                "cp.async.bulk.shared::cta.global.mbarrier::complete_tx::bytes "
                "[%0], [%1], %2, [%3];"
                :: "r"(tdst), "l"(tsrc), "r"(tgt_bytes), "r"(mbar_u) : "memory");
            // ref row: 40 floats = 160B.
            const float* rsrc = ref + rowbase + c * HW + w_start;
            const uint32_t rdst = sr_u + (uint32_t)(c * RROW) * 4u;
            asm volatile(
                "cp.async.bulk.shared::cta.global.mbarrier::complete_tx::bytes "
                "[%0], [%1], %2, [%3];"
                :: "r"(rdst), "l"(rsrc), "r"(160), "r"(mbar_u) : "memory");
        }
    }

    // All threads wait for completion (phase parity 0), acquire ordering.
    {
        unsigned ok;
        do {
            asm volatile(
                "{\n\t.reg .pred p;\n\t"
                "mbarrier.try_wait.parity.acquire.cta.shared::cta.b64 p, [%1], %2, 0x989680;\n\t"
                "selp.b32 %0, 1, 0, p;\n\t}"
                : "=r"(ok) : "r"(mbar_u), "r"(0u) : "memory");
        } while (!ok);
    }

    // ---- compute: identical to R9 ----
    const int lane = tid & 31;
    const int warp = tid >> 5;               // 0..4
    const int wbq  = warp * 4 + (lane & 3);  // 0..19
    const int dg   = (lane >> 2) & 3;
    const int cg   = lane >> 4;
    const int w0   = w_start + 2 * wbq;
    const int d0   = 6 * dg;

    const float* tp = st + (2 * wbq - d0 + 18);        // + c*TROW
    const float* rp = sr + 2 * wbq;                    // + c*RROW
    const int c0 = cg * CPT;

    float c00 = 0.f, c01 = 0.f, c02 = 0.f, c03 = 0.f, c04 = 0.f, c05 = 0.f;
    float c10 = 0.f, c11 = 0.f, c12 = 0.f, c13 = 0.f, c14 = 0.f, c15 = 0.f;

#pragma unroll
    for (int k = 0; k < CPT; ++k) {
        const int c = c0 + k;
        const float2 r  = *(const float2*)(rp + c * RROW);
        const float2 tA = *(const float2*)(tp + c * TROW);      // t0,t1
        const float2 tB = *(const float2*)(tp + c * TROW + 2);  // t2,t3
        const float2 tC = *(const float2*)(tp + c * TROW + 4);  // t4,t5
        const float2 tD = *(const float2*)(tp + c * TROW + 6);  // t6,t7
        c00 += fabsf(r.x - tD.x);
        c01 += fabsf(r.x - tC.y);
        c02 += fabsf(r.x - tC.x);
        c03 += fabsf(r.x - tB.y);
        c04 += fabsf(r.x - tB.x);
        c05 += fabsf(r.x - tA.y);
        c10 += fabsf(r.y - tD.y);
        c11 += fabsf(r.y - tD.x);
        c12 += fabsf(r.y - tC.y);
        c13 += fabsf(r.y - tC.x);
        c14 += fabsf(r.y - tB.y);
        c15 += fabsf(r.y - tB.x);
    }

    c00 += __shfl_xor_sync(0xffffffffu, c00, 16);
    c01 += __shfl_xor_sync(0xffffffffu, c01, 16);
    c02 += __shfl_xor_sync(0xffffffffu, c02, 16);
    c03 += __shfl_xor_sync(0xffffffffu, c03, 16);
    c04 += __shfl_xor_sync(0xffffffffu, c04, 16);
    c05 += __shfl_xor_sync(0xffffffffu, c05, 16);
    c10 += __shfl_xor_sync(0xffffffffu, c10, 16);
    c11 += __shfl_xor_sync(0xffffffffu, c11, 16);
    c12 += __shfl_xor_sync(0xffffffffu, c12, 16);
    c13 += __shfl_xor_sync(0xffffffffu, c13, 16);
    c14 += __shfl_xor_sync(0xffffffffu, c14, 16);
    c15 += __shfl_xor_sync(0xffffffffu, c15, 16);

    if (w0 < d0    ) c00 = 0.f;
    if (w0 < d0 + 1) c01 = 0.f;
    if (w0 < d0 + 2) c02 = 0.f;
    if (w0 < d0 + 3) c03 = 0.f;
    if (w0 < d0 + 4) c04 = 0.f;
    if (w0 < d0 + 5) c05 = 0.f;
    if (w0 + 1 < d0    ) c10 = 0.f;
    if (w0 + 1 < d0 + 1) c11 = 0.f;
    if (w0 + 1 < d0 + 2) c12 = 0.f;
    if (w0 + 1 < d0 + 3) c13 = 0.f;
    if (w0 + 1 < d0 + 4) c14 = 0.f;
    if (w0 + 1 < d0 + 5) c15 = 0.f;

    float m0 = fmaxf(fmaxf(fmaxf(c00, c01), fmaxf(c02, c03)), fmaxf(c04, c05));
    float m1 = fmaxf(fmaxf(fmaxf(c10, c11), fmaxf(c12, c13)), fmaxf(c14, c15));
    m0 = fmaxf(m0, __shfl_xor_sync(0xffffffffu, m0, 4));
    m0 = fmaxf(m0, __shfl_xor_sync(0xffffffffu, m0, 8));
    m1 = fmaxf(m1, __shfl_xor_sync(0xffffffffu, m1, 4));
    m1 = fmaxf(m1, __shfl_xor_sync(0xffffffffu, m1, 8));

    const float e00 = __expf(c00 - m0), e01 = __expf(c01 - m0), e02 = __expf(c02 - m0);
    const float e03 = __expf(c03 - m0), e04 = __expf(c04 - m0), e05 = __expf(c05 - m0);
    const float e10 = __expf(c10 - m1), e11 = __expf(c11 - m1), e12 = __expf(c12 - m1);
    const float e13 = __expf(c13 - m1), e14 = __expf(c14 - m1), e15 = __expf(c15 - m1);

    const float fd = (float)d0;
    float s0 = ((e00 + e01) + (e02 + e03)) + (e04 + e05);
    float n0 = fd * e00 + (fd + 1.f) * e01 + (fd + 2.f) * e02
             + (fd + 3.f) * e03 + (fd + 4.f) * e04 + (fd + 5.f) * e05;
    float s1 = ((e10 + e11) + (e12 + e13)) + (e14 + e15);
    float n1 = fd * e10 + (fd + 1.f) * e11 + (fd + 2.f) * e12
             + (fd + 3.f) * e13 + (fd + 4.f) * e14 + (fd + 5.f) * e15;

    s0 += __shfl_xor_sync(0xffffffffu, s0, 4);
    s0 += __shfl_xor_sync(0xffffffffu, s0, 8);
    n0 += __shfl_xor_sync(0xffffffffu, n0, 4);
    n0 += __shfl_xor_sync(0xffffffffu, n0, 8);
    s1 += __shfl_xor_sync(0xffffffffu, s1, 4);
    s1 += __shfl_xor_sync(0xffffffffu, s1, 8);
    n1 += __shfl_xor_sync(0xffffffffu, n1, 4);
    n1 += __shfl_xor_sync(0xffffffffu, n1, 8);

    if (dg == 0 && cg == 0) {
        float2 o;
        o.x = n0 / s0;
        o.y = n1 / s1;
        *(float2*)&out[(b * Hc + h) * Wc + w0] = o;
    }
}

extern "C" void kernel_launch(void* const* d_in, const int* in_sizes, int n_in,
                              void* d_out, int out_size)
{
    const float* ref = (const float*)d_in[0];
    const float* tgt = (const float*)d_in[1];
    float* out = (float*)d_out;

    dim3 grid(4, Hc, Bc);   // 1280 CTAs x 160 threads
    hsm_dispreg_kernel<<<grid, NT>>>(ref, tgt, out);
}

// round 12
// speedup vs baseline: 1.1895x; 1.1866x over previous
#include <cuda_runtime.h>
#include <cuda_bf16.h>
#include <cuda_pipeline.h>
#include <cstdint>

// HSMNet cost-volume + channel-sum + softmax disparity regression, fused.
// B=4, C=32, H=80, W=160, D=24. Output [B,H,W] f32.
//
// R11: R9 compute (thread = wpair x dg4 x cg2, conflict-free LDS.64, shfl
// merges) + pipelined per-thread cp.async staging in 2 channel-chunks
// ({0-7,16-23} then {8-15,24-31}), double-buffered with wait_prior(1) so
// chunk-0 compute overlaps chunk-1 DRAM latency. Validity selects and halo
// zeroing only in q==0 CTAs (uniform branch).

#define Bc 4
#define Cc 32
#define Hc 80
#define Wc 160
#define Dc 24
#define QW 40                 // pixels per CTA (quarter row)
#define NT 160
#define TROW 64               // tgt cols staged: [w_start-24, w_start+40)
#define RROW 40               // ref cols staged: [w_start, w_start+40)

__global__ __launch_bounds__(NT, 9)
void hsm_dispreg_kernel(const float* __restrict__ ref,
                        const float* __restrict__ tgt,
                        float* __restrict__ out)
{
    __shared__ __align__(16) float st[Cc * TROW];   // 2048 floats
    __shared__ __align__(16) float sr[Cc * RROW];   // 1280 floats

    const int q   = blockIdx.x;              // 0..3
    const int h   = blockIdx.y;
    const int b   = blockIdx.z;
    const int tid = threadIdx.x;

    const int w_start = q * QW;
    const int rowbase = (b * Cc * Hc + h) * Wc;
    const int HW = Hc * Wc;
    const int g0 = w_start - 24;

    // ref-row copy mapping: 16 rows x 10 segs = 160 = NT (one copy per thread)
    const int rr  = tid / 10;                // 0..15
    const int rsg = tid - rr * 10;           // 0..9

    // q==0: zero the 24-float left halo of every tgt row (synchronous STS).
    if (q == 0) {
#pragma unroll
        for (int k = 0; k < 5; ++k) {
            const int idx = tid + k * NT;    // covers 32*24 = 768
            if (idx < Cc * 24) {
                const int c = idx / 24;
                const int l = idx - c * 24;
                st[c * TROW + l] = 0.0f;
            }
        }
    }

    // ---- issue both chunks of async copies, one commit per chunk ----
#pragma unroll
    for (int g = 0; g < 2; ++g) {
        // tgt rows of this chunk: channels {g*8..g*8+7} U {16+g*8..16+g*8+7}
        if (q == 0) {
            // valid region is 40 floats at gcol 0 -> dst offset +24; 10 segs
            const int c = ((rr < 8) ? rr : rr + 8) + g * 8;
            __pipeline_memcpy_async(
                st + c * TROW + 24 + rsg * 4,
                tgt + rowbase + c * HW + rsg * 4, 16);
        } else {
#pragma unroll
            for (int k = 0; k < 2; ++k) {
                const int idx = tid + k * NT;
                if (idx < 256) {
                    const int r = idx >> 4;
                    const int seg = idx & 15;
                    const int c = ((r < 8) ? r : r + 8) + g * 8;
                    __pipeline_memcpy_async(
                        st + c * TROW + seg * 4,
                        tgt + rowbase + c * HW + g0 + seg * 4, 16);
                }
            }
        }
        // ref rows of this chunk: 16 rows x 10 segs
        {
            const int c = ((rr < 8) ? rr : rr + 8) + g * 8;
            __pipeline_memcpy_async(
                sr + c * RROW + rsg * 4,
                ref + rowbase + c * HW + w_start + rsg * 4, 16);
        }
        __pipeline_commit();
    }

    // ---- lane mapping (identical to R9) ----
    const int lane = tid & 31;
    const int warp = tid >> 5;               // 0..4
    const int wbq  = warp * 4 + (lane & 3);  // 0..19
    const int dg   = (lane >> 2) & 3;
    const int cg   = lane >> 4;
    const int w0   = w_start + 2 * wbq;
    const int d0   = 6 * dg;

    const float* tp = st + (2 * wbq - d0 + 18);        // + c*TROW
    const float* rp = sr + 2 * wbq;                    // + c*RROW

    float c00 = 0.f, c01 = 0.f, c02 = 0.f, c03 = 0.f, c04 = 0.f, c05 = 0.f;
    float c10 = 0.f, c11 = 0.f, c12 = 0.f, c13 = 0.f, c14 = 0.f, c15 = 0.f;

    // ---- chunk 0 ready; compute channels cg*16 + [0,8) ----
    __pipeline_wait_prior(1);
    __syncthreads();

#pragma unroll
    for (int k = 0; k < 8; ++k) {
        const int c = cg * 16 + k;
        const float2 r  = *(const float2*)(rp + c * RROW);
        const float2 tA = *(const float2*)(tp + c * TROW);
        const float2 tB = *(const float2*)(tp + c * TROW + 2);
        const float2 tC = *(const float2*)(tp + c * TROW + 4);
        const float2 tD = *(const float2*)(tp + c * TROW + 6);
        c00 += fabsf(r.x - tD.x);
        c01 += fabsf(r.x - tC.y);
        c02 += fabsf(r.x - tC.x);
        c03 += fabsf(r.x - tB.y);
        c04 += fabsf(r.x - tB.x);
        c05 += fabsf(r.x - tA.y);
        c10 += fabsf(r.y - tD.y);
        c11 += fabsf(r.y - tD.x);
        c12 += fabsf(r.y - tC.y);
        c13 += fabsf(r.y - tC.x);
        c14 += fabsf(r.y - tB.y);
        c15 += fabsf(r.y - tB.x);
    }

    // ---- chunk 1 ready; compute channels cg*16 + [8,16) ----
    __pipeline_wait_prior(0);
    __syncthreads();

#pragma unroll
    for (int k = 8; k < 16; ++k) {
        const int c = cg * 16 + k;
        const float2 r  = *(const float2*)(rp + c * RROW);
        const float2 tA = *(const float2*)(tp + c * TROW);
        const float2 tB = *(const float2*)(tp + c * TROW + 2);
        const float2 tC = *(const float2*)(tp + c * TROW + 4);
        const float2 tD = *(const float2*)(tp + c * TROW + 6);
        c00 += fabsf(r.x - tD.x);
        c01 += fabsf(r.x - tC.y);
        c02 += fabsf(r.x - tC.x);
        c03 += fabsf(r.x - tB.y);
        c04 += fabsf(r.x - tB.x);
        c05 += fabsf(r.x - tA.y);
        c10 += fabsf(r.y - tD.y);
        c11 += fabsf(r.y - tD.x);
        c12 += fabsf(r.y - tC.y);
        c13 += fabsf(r.y - tC.x);
        c14 += fabsf(r.y - tB.y);
        c15 += fabsf(r.y - tB.x);
    }

    // ---- sum partial costs across cg (lanes xor 16) ----
    c00 += __shfl_xor_sync(0xffffffffu, c00, 16);
    c01 += __shfl_xor_sync(0xffffffffu, c01, 16);
    c02 += __shfl_xor_sync(0xffffffffu, c02, 16);
    c03 += __shfl_xor_sync(0xffffffffu, c03, 16);
    c04 += __shfl_xor_sync(0xffffffffu, c04, 16);
    c05 += __shfl_xor_sync(0xffffffffu, c05, 16);
    c10 += __shfl_xor_sync(0xffffffffu, c10, 16);
    c11 += __shfl_xor_sync(0xffffffffu, c11, 16);
    c12 += __shfl_xor_sync(0xffffffffu, c12, 16);
    c13 += __shfl_xor_sync(0xffffffffu, c13, 16);
    c14 += __shfl_xor_sync(0xffffffffu, c14, 16);
    c15 += __shfl_xor_sync(0xffffffffu, c15, 16);

    // validity (d > w -> cost 0): only possible in q==0 CTAs (w0 <= 38)
    if (q == 0) {
        if (w0 < d0    ) c00 = 0.f;
        if (w0 < d0 + 1) c01 = 0.f;
        if (w0 < d0 + 2) c02 = 0.f;
        if (w0 < d0 + 3) c03 = 0.f;
        if (w0 < d0 + 4) c04 = 0.f;
        if (w0 < d0 + 5) c05 = 0.f;
        if (w0 + 1 < d0    ) c10 = 0.f;
        if (w0 + 1 < d0 + 1) c11 = 0.f;
        if (w0 + 1 < d0 + 2) c12 = 0.f;
        if (w0 + 1 < d0 + 3) c13 = 0.f;
        if (w0 + 1 < d0 + 4) c14 = 0.f;
        if (w0 + 1 < d0 + 5) c15 = 0.f;
    }

    // ---- exact two-pass softmax + expectation across the 4 dg lanes ----
    float m0 = fmaxf(fmaxf(fmaxf(c00, c01), fmaxf(c02, c03)), fmaxf(c04, c05));
    float m1 = fmaxf(fmaxf(fmaxf(c10, c11), fmaxf(c12, c13)), fmaxf(c14, c15));
    m0 = fmaxf(m0, __shfl_xor_sync(0xffffffffu, m0, 4));
    m0 = fmaxf(m0, __shfl_xor_sync(0xffffffffu, m0, 8));
    m1 = fmaxf(m1, __shfl_xor_sync(0xffffffffu, m1, 4));
    m1 = fmaxf(m1, __shfl_xor_sync(0xffffffffu, m1, 8));

    const float e00 = __expf(c00 - m0), e01 = __expf(c01 - m0), e02 = __expf(c02 - m0);
    const float e03 = __expf(c03 - m0), e04 = __expf(c04 - m0), e05 = __expf(c05 - m0);
    const float e10 = __expf(c10 - m1), e11 = __expf(c11 - m1), e12 = __expf(c12 - m1);
    const float e13 = __expf(c13 - m1), e14 = __expf(c14 - m1), e15 = __expf(c15 - m1);

    const float fd = (float)d0;
    float s0 = ((e00 + e01) + (e02 + e03)) + (e04 + e05);
    float n0 = fd * e00 + (fd + 1.f) * e01 + (fd + 2.f) * e02
             + (fd + 3.f) * e03 + (fd + 4.f) * e04 + (fd + 5.f) * e05;
    float s1 = ((e10 + e11) + (e12 + e13)) + (e14 + e15);
    float n1 = fd * e10 + (fd + 1.f) * e11 + (fd + 2.f) * e12
             + (fd + 3.f) * e13 + (fd + 4.f) * e14 + (fd + 5.f) * e15;

    s0 += __shfl_xor_sync(0xffffffffu, s0, 4);
    s0 += __shfl_xor_sync(0xffffffffu, s0, 8);
    n0 += __shfl_xor_sync(0xffffffffu, n0, 4);
    n0 += __shfl_xor_sync(0xffffffffu, n0, 8);
    s1 += __shfl_xor_sync(0xffffffffu, s1, 4);
    s1 += __shfl_xor_sync(0xffffffffu, s1, 8);
    n1 += __shfl_xor_sync(0xffffffffu, n1, 4);
    n1 += __shfl_xor_sync(0xffffffffu, n1, 8);

    if (dg == 0 && cg == 0) {
        float2 o;
        o.x = n0 / s0;
        o.y = n1 / s1;
        *(float2*)&out[(b * Hc + h) * Wc + w0] = o;
    }
}

extern "C" void kernel_launch(void* const* d_in, const int* in_sizes, int n_in,
                              void* d_out, int out_size)
{
    const float* ref = (const float*)d_in[0];
    const float* tgt = (const float*)d_in[1];
    float* out = (float*)d_out;

    dim3 grid(4, Hc, Bc);   // 1280 CTAs x 160 threads
    hsm_dispreg_kernel<<<grid, NT>>>(ref, tgt, out);
}